// round 15
// baseline (speedup 1.0000x reference)
#include <cuda_runtime.h>
#include <cuda_bf16.h>
#include <cuda_fp16.h>
#include <cuda_fp8.h>
#include <cstdint>
#include <math.h>

typedef unsigned long long ull;

#define B_  16
#define C_  1024
#define P_  512
#define HW_ 1024
#define G_  8

#define WSCALE     64.0f
#define INV_WSCALE 0.015625f

// ---------------- scratch (static device globals; no allocation) ----------------
__device__ __half d_z16[(size_t)B_ * C_ * HW_];        // 32 MB fp16
__device__ float d_S[B_ * G_ * 4];                     // moment sums; S0 exact
__device__ float d_gn[B_ * G_ * 2];                    // GN sum / sumsq
__device__ float d_xsum[B_ * C_];                      // per (b,c) spatial sums
__device__ float d_wgsum[G_ * C_];                     // per (g,c) Wg row sums
__device__ float d_wzrs[G_ * 128];                     // rowsum of Wz per (g,oc)

// quantized operands
__device__ uint8_t d_W8[3u * 512u * 1024u];            // fp8 W (x64)
__device__ uint8_t d_XT8[(size_t)B_ * 1024u * 1024u];  // fp8 X^T [b][n][k]
__device__ __nv_bfloat16 d_Wz16[G_ * 128 * 64];        // bf16 Wz

// ---------------- PTX helpers ----------------
__device__ __forceinline__ uint32_t smem_u32(const void* p) {
    uint32_t a;
    asm("{ .reg .u64 t; cvta.to.shared.u64 t, %1; cvt.u32.u64 %0, t; }" : "=r"(a) : "l"(p));
    return a;
}
#define CP_ASYNC16(sa, ga) \
    asm volatile("cp.async.cg.shared.global [%0], [%1], 16;" :: "r"(sa), "l"(ga))
#define CP_COMMIT()   asm volatile("cp.async.commit_group;" ::: "memory")
#define CP_WAIT(n)    asm volatile("cp.async.wait_group %0;" :: "n"(n) : "memory")

__device__ __forceinline__ void ldsm_x4(uint32_t& r0, uint32_t& r1, uint32_t& r2, uint32_t& r3,
                                        uint32_t addr) {
    asm volatile("ldmatrix.sync.aligned.m8n8.x4.shared.b16 {%0,%1,%2,%3}, [%4];"
                 : "=r"(r0), "=r"(r1), "=r"(r2), "=r"(r3) : "r"(addr));
}
// fp8 e4m3 MMA, k=32, f16 accumulators (2 regs)
__device__ __forceinline__ void mma16832h(uint32_t* c, const uint32_t* a, uint32_t b0, uint32_t b1) {
    asm volatile("mma.sync.aligned.m16n8k32.row.col.f16.e4m3.e4m3.f16 "
                 "{%0,%1}, {%2,%3,%4,%5}, {%6,%7}, {%0,%1};"
                 : "+r"(c[0]), "+r"(c[1])
                 : "r"(a[0]), "r"(a[1]), "r"(a[2]), "r"(a[3]), "r"(b0), "r"(b1));
}
__device__ __forceinline__ void mma16816(float* c, const uint32_t* a, uint32_t b0, uint32_t b1) {
    asm volatile("mma.sync.aligned.m16n8k16.row.col.f32.bf16.bf16.f32 "
                 "{%0,%1,%2,%3}, {%4,%5,%6,%7}, {%8,%9}, {%0,%1,%2,%3};"
                 : "+f"(c[0]), "+f"(c[1]), "+f"(c[2]), "+f"(c[3])
                 : "r"(a[0]), "r"(a[1]), "r"(a[2]), "r"(a[3]), "r"(b0), "r"(b1));
}
__device__ __forceinline__ uint8_t to_e4m3(float v) {
    return (uint8_t)__nv_cvt_float_to_fp8(v, __NV_SATFINITE, __NV_E4M3);
}

// =====================================================================
// k_prep: fused prepass — roles by blockIdx.x
// =====================================================================
__global__ void __launch_bounds__(256) k_prep(
    const float* __restrict__ Wt, const float* __restrict__ Wp,
    const float* __restrict__ Wg, const float* __restrict__ Wz)
{
    int bx = blockIdx.x, tid = threadIdx.x;
    if (bx < 1536) {
        int w = bx >> 9, inner = bx & 511;
        const float* W = (w == 0) ? Wt : (w == 1) ? Wp : Wg;
        size_t idx = ((size_t)inner * 256 + tid) * 4;
        float4 v = *(const float4*)&W[idx];
        uint32_t pk = (uint32_t)to_e4m3(v.x * WSCALE)
                    | ((uint32_t)to_e4m3(v.y * WSCALE) << 8)
                    | ((uint32_t)to_e4m3(v.z * WSCALE) << 16)
                    | ((uint32_t)to_e4m3(v.w * WSCALE) << 24);
        *(uint32_t*)(d_W8 + (size_t)w * 524288u + idx) = pk;
    } else if (bx == 1536) {
        for (int i = tid; i < B_ * C_; i += 256) d_xsum[i] = 0.f;
        for (int i = tid; i < 512; i += 256)     d_S[i]    = 0.f;
        if (tid < 256)                            d_gn[tid] = 0.f;
    } else if (bx < 1569) {
        int idx = bx - 1537;
        int g = idx >> 2, c = (idx & 3) * 256 + tid;
        const float* base = Wg + (size_t)g * 64 * 1024 + c;
        float s = 0.f;
#pragma unroll 8
        for (int r = 0; r < 64; r++) s += base[(size_t)r * 1024];
        d_wgsum[g * 1024 + c] = s;
    } else if (bx < 1601) {
        int idx = bx - 1569;
        int base = idx * 2048 + tid * 8;
        float4 v0 = *(const float4*)&Wz[base];
        float4 v1 = *(const float4*)&Wz[base + 4];
        __nv_bfloat162 h0 = __floats2bfloat162_rn(v0.x, v0.y);
        __nv_bfloat162 h1 = __floats2bfloat162_rn(v0.z, v0.w);
        __nv_bfloat162 h2 = __floats2bfloat162_rn(v1.x, v1.y);
        __nv_bfloat162 h3 = __floats2bfloat162_rn(v1.z, v1.w);
        *(uint4*)(d_Wz16 + base) = make_uint4(*(uint32_t*)&h0, *(uint32_t*)&h1,
                                              *(uint32_t*)&h2, *(uint32_t*)&h3);
    } else {
        for (int oc = tid; oc < 1024; oc += 256) {
            const float* p = Wz + (size_t)oc * 64;
            float s = 0.f;
#pragma unroll
            for (int k = 0; k < 64; k++) s += p[k];
            d_wzrs[oc] = s;
        }
    }
}

// =====================================================================
// X transpose -> fp8 [b][n][k] with coalesced 128B writes,
// + exact fp32 channel sums.  Block = 128k x 64n.
// Xs row stride = 68 floats (272B, 16B-aligned for float4 stores).
// =====================================================================
__global__ void __launch_bounds__(256) k_transX(const float* __restrict__ x)
{
    __shared__ float Xs[128][68];
    const int k0 = blockIdx.x * 128;
    const int n0 = blockIdx.y * 64;
    const int b  = blockIdx.z;
    const int tid = threadIdx.x;
    const float* xb = x + ((size_t)b * 1024 + k0) * 1024 + n0;
#pragma unroll
    for (int i = 0; i < 8; i++) {
        int slot = tid + i * 256;           // 0..2047 float4 slots
        int r  = slot >> 4;                 // 0..127
        int c4 = (slot & 15) << 2;          // 0..60
        *(float4*)&Xs[r][c4] = *(const float4*)&xb[(size_t)r * 1024 + c4];
    }
    __syncthreads();

    // exact fp32 channel partial sums
    {
        int r = tid >> 1, h = tid & 1;
        float s = 0.f;
#pragma unroll
        for (int c = 0; c < 32; c++) s += Xs[r][h * 32 + c];
        s += __shfl_xor_sync(0xffffffffu, s, 1);
        if (h == 0) atomicAdd(&d_xsum[b * 1024 + k0 + r], s);
    }

    // quantize + coalesced store: each slot packs 16 consecutive k for one n
#pragma unroll
    for (int i = 0; i < 2; i++) {
        int slot = tid + i * 256;           // 0..511
        int n = slot >> 3;                  // 0..63
        int u = slot & 7;                   // 0..7 -> k bytes u*16..u*16+15
        uint32_t w[4];
#pragma unroll
        for (int q = 0; q < 4; q++) {
            int kb = u * 16 + q * 4;
            w[q] = (uint32_t)to_e4m3(Xs[kb + 0][n])
                 | ((uint32_t)to_e4m3(Xs[kb + 1][n]) << 8)
                 | ((uint32_t)to_e4m3(Xs[kb + 2][n]) << 16)
                 | ((uint32_t)to_e4m3(Xs[kb + 3][n]) << 24);
        }
        *(uint4*)(d_XT8 + ((size_t)(b * 1024 + n0 + n)) * 1024 + k0 + u * 16) =
            make_uint4(w[0], w[1], w[2], w[3]);
    }
}

// =====================================================================
// Exact S0[b][g] = sum_c wgsum[g][c] * xsum[b][c]
// =====================================================================
__global__ void __launch_bounds__(256) k_s0()
{
    int bg = blockIdx.x;
    int b = bg >> 3, g = bg & 7;
    int tid = threadIdx.x;
    float s = 0.f;
    for (int c = tid; c < 1024; c += 256)
        s += d_wgsum[g * 1024 + c] * d_xsum[b * 1024 + c];
#pragma unroll
    for (int off = 16; off > 0; off >>= 1)
        s += __shfl_down_sync(0xffffffffu, s, off);
    __shared__ float red[8];
    if ((tid & 31) == 0) red[tid >> 5] = s;
    __syncthreads();
    if (tid == 0) {
        float S = 0.f;
#pragma unroll
        for (int i = 0; i < 8; i++) S += red[i];
        d_S[bg * 4 + 0] = S;
    }
}

// =====================================================================
// GEMM-PG (fp8, f16 acc): CTA 128m x 256n, 512 thr / 16 warps
// (warp tile 32m x 64n), 4-stage cp.async pipeline.
// =====================================================================
#define NCH        16
#define ROWB       80
#define TILE_B     10240           // 128 rows * 80B
#define PG_STG     40960           // Ap + Ag + B(256)

__device__ __forceinline__ void pg_load_chunk(
    uint32_t sb, const uint8_t* gAp, const uint8_t* gAg,
    const uint8_t* gB, int k0, int tid)
{
#pragma unroll
    for (int i = 0; i < 4; i++) {
        int unit = tid + i * 512;            // 0..2047
        const uint8_t* src;
        uint32_t dst;
        if (unit < 512) {
            int r = unit >> 2, u = unit & 3;
            dst = sb + (uint32_t)r * ROWB + (uint32_t)u * 16;
            src = gAp + (size_t)r * 1024 + k0 + u * 16;
        } else if (unit < 1024) {
            int rem = unit - 512;
            int r = rem >> 2, u = rem & 3;
            dst = sb + TILE_B + (uint32_t)r * ROWB + (uint32_t)u * 16;
            src = gAg + (size_t)r * 1024 + k0 + u * 16;
        } else {
            int rem = unit - 1024;           // 0..1023 -> 256 rows
            int r = rem >> 2, u = rem & 3;
            dst = sb + 2 * TILE_B + (uint32_t)r * ROWB + (uint32_t)u * 16;
            src = gB + (size_t)r * 1024 + k0 + u * 16;
        }
        CP_ASYNC16(dst, (const void*)src);
    }
}

__global__ void __launch_bounds__(512, 1) k_gemm_pg()
{
    extern __shared__ char smraw[];
    uint32_t sbase = smem_u32(smraw);

    const int tid  = threadIdx.x;
    const int wid  = tid >> 5;
    const int lane = tid & 31;
    const int wm   = wid & 3;       // 4 m-subtiles of 32
    const int wn   = wid >> 2;      // 4 n-subtiles of 64

    const int n0 = blockIdx.x * 256;
    const int m0 = blockIdx.y * 128;
    const int b  = blockIdx.z;

    const uint8_t* gAp = d_W8 + 1u * 524288u + (size_t)m0 * 1024;
    const uint8_t* gAg = d_W8 + 2u * 524288u + (size_t)m0 * 1024;
    const uint8_t* gB  = d_XT8 + ((size_t)b * 1024 + n0) * 1024;

    uint32_t accp[2][8][2], accg[2][8][2];      // f16x2 accumulators (warp 32x64)
#pragma unroll
    for (int i = 0; i < 2; i++)
#pragma unroll
        for (int j = 0; j < 8; j++) {
            accp[i][j][0] = 0u; accp[i][j][1] = 0u;
            accg[i][j][0] = 0u; accg[i][j][1] = 0u;
        }

    const uint32_t aLane = (uint32_t)((wm * 32 + (lane & 15)) * ROWB + (lane >> 4) * 16);
    const int bgrp = lane >> 3;
    const uint32_t bLane = (uint32_t)((wn * 64 + (bgrp >> 1) * 8 + (lane & 7)) * ROWB + (bgrp & 1) * 16);

    pg_load_chunk(sbase, gAp, gAg, gB, 0, tid);
    CP_COMMIT();
    pg_load_chunk(sbase + PG_STG, gAp, gAg, gB, 64, tid);
    CP_COMMIT();
    pg_load_chunk(sbase + 2 * PG_STG, gAp, gAg, gB, 128, tid);
    CP_COMMIT();

    int stg = 0;
    for (int j = 0; j < NCH; j++) {
        if (j <= NCH - 3)      CP_WAIT(2);
        else if (j == NCH - 2) CP_WAIT(1);
        else                   CP_WAIT(0);
        __syncthreads();
        if (j + 3 < NCH) {
            int ns = stg + 3; if (ns >= 4) ns -= 4;
            pg_load_chunk(sbase + (uint32_t)ns * PG_STG, gAp, gAg, gB, (j + 3) * 64, tid);
            CP_COMMIT();
        }
        const uint32_t sb = sbase + (uint32_t)stg * PG_STG;
#pragma unroll
        for (int s = 0; s < 2; s++) {
            const uint32_t kb = (uint32_t)s * 32;
            uint32_t Ap[2][4], Ag[2][4], Bv[8][2];
#pragma unroll
            for (int i = 0; i < 2; i++) {
                ldsm_x4(Ap[i][0], Ap[i][1], Ap[i][2], Ap[i][3],
                        sb + 0 * TILE_B + aLane + (uint32_t)i * (16 * ROWB) + kb);
                ldsm_x4(Ag[i][0], Ag[i][1], Ag[i][2], Ag[i][3],
                        sb + 1 * TILE_B + aLane + (uint32_t)i * (16 * ROWB) + kb);
            }
#pragma unroll
            for (int jp = 0; jp < 4; jp++)
                ldsm_x4(Bv[jp * 2][0], Bv[jp * 2][1], Bv[jp * 2 + 1][0], Bv[jp * 2 + 1][1],
                        sb + 2 * TILE_B + bLane + (uint32_t)jp * (16 * ROWB) + kb);
#pragma unroll
            for (int i = 0; i < 2; i++)
#pragma unroll
                for (int jj = 0; jj < 8; jj++) {
                    mma16832h(accp[i][jj], Ap[i], Bv[jj][0], Bv[jj][1]);
                    mma16832h(accg[i][jj], Ag[i], Bv[jj][0], Bv[jj][1]);
                }
        }
        if (++stg == 4) stg = 0;
    }

    // moment epilogue (S1..S3; unscale W factor on p and g)
    {
        float s1 = 0.f, s2 = 0.f, s3 = 0.f;
#pragma unroll
        for (int i = 0; i < 2; i++)
#pragma unroll
            for (int jj = 0; jj < 8; jj++)
#pragma unroll
                for (int h = 0; h < 2; h++) {
                    float2 pv2 = __half22float2(*(__half2*)&accp[i][jj][h]);
                    float2 gv2 = __half22float2(*(__half2*)&accg[i][jj][h]);
#pragma unroll
                    for (int l = 0; l < 2; l++) {
                        float pv = (l ? pv2.y : pv2.x) * INV_WSCALE;
                        float gv = (l ? gv2.y : gv2.x) * INV_WSCALE;
                        float t1 = pv * gv; s1 += t1;
                        t1 *= pv; s2 += t1;
                        t1 *= pv; s3 += t1;
                    }
                }
#pragma unroll
        for (int off = 16; off > 0; off >>= 1) {
            s1 += __shfl_down_sync(0xffffffffu, s1, off);
            s2 += __shfl_down_sync(0xffffffffu, s2, off);
            s3 += __shfl_down_sync(0xffffffffu, s3, off);
        }
        if (lane == 0) {
            int g = (m0 >> 6) + (wm >> 1);
            float* Sp = d_S + (b * 8 + g) * 4;
            atomicAdd(Sp + 1, s1);
            atomicAdd(Sp + 2, s2);
            atomicAdd(Sp + 3, s3);
        }
    }
}

// =====================================================================
// GEMM-TZ (fp8 f16-acc + fused z): t = Wt @ X (CTA 128x128, warp 64x32,
// K=128 chunks, 3-stage), then y'' transform + transposed smem stage +
// z-GEMM (bf16 HMMA, f32 acc), z written fp16 + GN partial sums.
// =====================================================================
#define NCH2      8
#define ROWT      144
#define T_TILE2   18432            // 128 rows * 144B
#define T_STG2    36864            // A + B
#define AZ_OFF    0
#define TS_OFF    36864
#define ZT_STRIDE 18432            // 128 rows * 144 B
#define ROWZ      144
#define TZ_SMEM   110592           // 3 stages

__device__ __forceinline__ void t_load_chunk(
    uint32_t sb, const uint8_t* gA, const uint8_t* gB, int k0, int tid)
{
#pragma unroll
    for (int i = 0; i < 8; i++) {
        int unit = tid + i * 256;          // 0..2047
        int tile = unit >> 10;
        int rem  = unit & 1023;
        int r = rem >> 3, u = rem & 7;
        uint32_t dst = sb + (uint32_t)tile * T_TILE2 + (uint32_t)r * ROWT + (uint32_t)u * 16;
        const uint8_t* src = (tile == 0 ? gA : gB) + (size_t)r * 1024 + k0 + u * 16;
        CP_ASYNC16(dst, (const void*)src);
    }
}

__global__ void __launch_bounds__(256, 2) k_gemm_tz()
{
    extern __shared__ char smraw[];
    uint32_t sbase = smem_u32(smraw);

    const int tid  = threadIdx.x;
    const int wid  = tid >> 5;
    const int lane = tid & 31;
    const int wm   = wid & 1;
    const int wn   = wid >> 1;

    const int n0 = blockIdx.x * 128;
    const int m0 = blockIdx.y * 128;
    const int b  = blockIdx.z;

    const uint8_t* gA = d_W8 + (size_t)m0 * 1024;
    const uint8_t* gB = d_XT8 + ((size_t)b * 1024 + n0) * 1024;

    uint32_t acc[4][4][2];                       // f16x2 accumulators
#pragma unroll
    for (int i = 0; i < 4; i++)
#pragma unroll
        for (int j = 0; j < 4; j++) { acc[i][j][0] = 0u; acc[i][j][1] = 0u; }

    const uint32_t aLane = (uint32_t)((wm * 64 + (lane & 15)) * ROWT + (lane >> 4) * 16);
    const int bg = lane >> 3;
    const uint32_t bLane = (uint32_t)((wn * 32 + (bg >> 1) * 8 + (lane & 7)) * ROWT + (bg & 1) * 16);

    t_load_chunk(sbase, gA, gB, 0, tid);
    CP_COMMIT();
    t_load_chunk(sbase + T_STG2, gA, gB, 128, tid);
    CP_COMMIT();

    int stg = 0;
    for (int j = 0; j < NCH2; j++) {
        if (j + 1 < NCH2) CP_WAIT(1); else CP_WAIT(0);
        __syncthreads();
        if (j + 2 < NCH2) {
            int ns = stg + 2; if (ns >= 3) ns -= 3;
            t_load_chunk(sbase + (uint32_t)ns * T_STG2, gA, gB, (j + 2) * 128, tid);
            CP_COMMIT();
        }
        const uint32_t sb = sbase + (uint32_t)stg * T_STG2;
#pragma unroll
        for (int s = 0; s < 4; s++) {
            const uint32_t kb = (uint32_t)s * 32;
            uint32_t A[4][4], Bv[4][2];
#pragma unroll
            for (int i = 0; i < 4; i++)
                ldsm_x4(A[i][0], A[i][1], A[i][2], A[i][3],
                        sb + aLane + (uint32_t)i * (16 * ROWT) + kb);
#pragma unroll
            for (int jp = 0; jp < 2; jp++)
                ldsm_x4(Bv[jp * 2][0], Bv[jp * 2][1], Bv[jp * 2 + 1][0], Bv[jp * 2 + 1][1],
                        sb + T_TILE2 + bLane + (uint32_t)jp * (16 * ROWT) + kb);
#pragma unroll
            for (int i = 0; i < 4; i++)
#pragma unroll
                for (int jj = 0; jj < 4; jj++)
                    mma16832h(acc[i][jj], A[i], Bv[jj][0], Bv[jj][1]);
        }
        if (++stg == 3) stg = 0;
    }
    __syncthreads();        // all warps done reading stage smem

    const float tg   = 2.0f * 1e-4f;
    const float beta = expf(-tg);

    // ---- epilogue A: y'' transform + transposed smem stage [n][ch] ----
    {
        const int gidx = (b * 8) + (m0 >> 6) + wm;     // warp's group
        const float c1 = beta * tg * d_S[gidx * 4 + 1];
        const float c2 = beta * (tg * tg * 0.5f) * d_S[gidx * 4 + 2];
        const float c3 = beta * (tg * tg * tg * (1.f / 6.f)) * d_S[gidx * 4 + 3];
        const float a2 = c2 / c1, a3 = c3 / c1;

        char* Tsb = smraw + TS_OFF + wm * ZT_STRIDE;
        const int mq = lane >> 2;
        const int nq = (lane & 3) * 2;
#pragma unroll
        for (int i = 0; i < 4; i++)
#pragma unroll
            for (int jj = 0; jj < 4; jj++)
#pragma unroll
                for (int h = 0; h < 2; h++) {
                    float2 tv2 = __half22float2(*(__half2*)&acc[i][jj][h]);
#pragma unroll
                    for (int l = 0; l < 2; l++) {
                        int chl = (i * 16 + mq + (h << 3)) & 63;
                        int n   = wn * 32 + jj * 8 + nq + l;
                        float t = (l ? tv2.y : tv2.x) * INV_WSCALE;
                        float y = t * (1.f + a2 * t + a3 * t * t);
                        *(__nv_bfloat16*)(Tsb + n * ROWZ + chl * 2) = __float2bfloat16(y);
                    }
                }
    }
    // ---- epilogue B: async-load Wz tiles for the 2 groups ----
    {
        const int gb = (m0 >> 6);
#pragma unroll
        for (int i = 0; i < 8; i++) {
            int unit = tid + i * 256;             // 0..2047
            int tile = unit >> 10;
            int rem  = unit & 1023;
            int r = rem >> 3, u = rem & 7;
            CP_ASYNC16(sbase + AZ_OFF + (uint32_t)tile * ZT_STRIDE + (uint32_t)r * ROWZ + (uint32_t)u * 16,
                       (const void*)(d_Wz16 + (gb + tile) * 8192 + r * 64 + u * 8));
        }
        CP_COMMIT();
        CP_WAIT(0);
        __syncthreads();
    }
    // ---- epilogue C: z-GEMM, 2 jobs per warp (job = 64oc x 32n of one group) ----
#pragma unroll
    for (int jb = 0; jb < 2; jb++) {
        const int job  = wid * 2 + jb;            // 0..15
        const int gloc = job >> 3;
        const int och  = (job & 7) >> 2;
        const int nq   = job & 3;
        const int g    = (m0 >> 6) + gloc;
        const int gidx = b * 8 + g;
        const float c0 = beta * d_S[gidx * 4 + 0];
        const float c1 = beta * tg * d_S[gidx * 4 + 1];

        const uint32_t aBase = sbase + AZ_OFF + (uint32_t)gloc * ZT_STRIDE;
        const uint32_t bBase = sbase + TS_OFF + (uint32_t)gloc * ZT_STRIDE;
        const uint32_t aL = (uint32_t)((och * 64 + (lane & 15)) * ROWZ + (lane >> 4) * 16);
        const int bq = lane >> 3;
        const uint32_t bL = (uint32_t)((nq * 32 + (bq >> 1) * 8 + (lane & 7)) * ROWZ + (bq & 1) * 16);

        float az[4][4][4];
#pragma unroll
        for (int i = 0; i < 4; i++)
#pragma unroll
            for (int jj = 0; jj < 4; jj++)
#pragma unroll
                for (int q = 0; q < 4; q++) az[i][jj][q] = 0.f;

#pragma unroll
        for (int ks = 0; ks < 4; ks++) {
            const uint32_t kb = (uint32_t)ks * 32;
            uint32_t A[4][4], Bv[4][2];
#pragma unroll
            for (int i = 0; i < 4; i++)
                ldsm_x4(A[i][0], A[i][1], A[i][2], A[i][3],
                        aBase + aL + (uint32_t)i * (16 * ROWZ) + kb);
#pragma unroll
            for (int jp = 0; jp < 2; jp++)
                ldsm_x4(Bv[jp * 2][0], Bv[jp * 2][1], Bv[jp * 2 + 1][0], Bv[jp * 2 + 1][1],
                        bBase + bL + (uint32_t)jp * (16 * ROWZ) + kb);
#pragma unroll
            for (int i = 0; i < 4; i++)
#pragma unroll
                for (int jj = 0; jj < 4; jj++)
                    mma16816(az[i][jj], A[i], Bv[jj][0], Bv[jj][1]);
        }

        // write z (fp16) + GN partials for this job
        const int mloc = och * 64 + (lane >> 2);
        const int nloc = nq * 32 + (lane & 3) * 2;
        float rsv[4][2];
#pragma unroll
        for (int i = 0; i < 4; i++)
#pragma unroll
            for (int h = 0; h < 2; h++)
                rsv[i][h] = d_wzrs[g * 128 + mloc + i * 16 + h * 8];

        __half* zb = d_z16 + ((size_t)(b * 1024 + g * 128)) * 1024;
        float ls = 0.f, lss = 0.f;
#pragma unroll
        for (int i = 0; i < 4; i++)
#pragma unroll
            for (int jj = 0; jj < 4; jj++)
#pragma unroll
                for (int h = 0; h < 2; h++) {
                    float z0 = c0 * rsv[i][h] + c1 * az[i][jj][2 * h + 0];
                    float z1 = c0 * rsv[i][h] + c1 * az[i][jj][2 * h + 1];
                    ls += z0 + z1;
                    lss += z0 * z0 + z1 * z1;
                    int oc = mloc + i * 16 + h * 8;
                    int n  = nloc + jj * 8;
                    *(__half2*)(zb + (size_t)oc * 1024 + n0 + n) = __floats2half2_rn(z0, z1);
                }
#pragma unroll
        for (int off = 16; off > 0; off >>= 1) {
            ls  += __shfl_down_sync(0xffffffffu, ls, off);
            lss += __shfl_down_sync(0xffffffffu, lss, off);
        }
        if (lane == 0) {
            atomicAdd(&d_gn[gidx * 2 + 0], ls);
            atomicAdd(&d_gn[gidx * 2 + 1], lss);
        }
    }
}

// =====================================================================
// finish: out = (z - mean)*rstd*gn_w + gn_b + x   (z in fp16)
// =====================================================================
__global__ void __launch_bounds__(256) k_finish(
    const float* __restrict__ x, const float* __restrict__ gn_w,
    const float* __restrict__ gn_b, float* __restrict__ out)
{
    int i4 = blockIdx.x * 256 + threadIdx.x;
    if (i4 >= (B_ * C_ * HW_) / 4) return;
    size_t idx = (size_t)i4 * 4;
    int ch = (int)((idx >> 10) & 1023);
    int b  = (int)(idx >> 20);
    int bg = b * 8 + (ch >> 7);
    const float invN = 1.0f / 131072.0f;
    float s  = d_gn[bg * 2 + 0];
    float ss = d_gn[bg * 2 + 1];
    float mean = s * invN;
    float var  = ss * invN - mean * mean;
    float rstd = rsqrtf(var + 1e-5f);
    float a = gn_w[ch] * rstd;
    float c = gn_b[ch] - mean * a;
    uint2 zr = *(const uint2*)&d_z16[idx];
    float2 z01 = __half22float2(*(__half2*)&zr.x);
    float2 z23 = __half22float2(*(__half2*)&zr.y);
    float4 xv = *(const float4*)&x[idx];
    float4 o;
    o.x = z01.x * a + c + xv.x;
    o.y = z01.y * a + c + xv.y;
    o.z = z23.x * a + c + xv.z;
    o.w = z23.y * a + c + xv.w;
    *(float4*)&out[idx] = o;
}

// =====================================================================
extern "C" void kernel_launch(void* const* d_in, const int* in_sizes, int n_in,
                              void* d_out, int out_size)
{
    const float* x   = (const float*)d_in[0];
    const float* Wt  = (const float*)d_in[1];
    const float* Wp  = (const float*)d_in[2];
    const float* Wg  = (const float*)d_in[3];
    const float* Wz  = (const float*)d_in[4];
    const float* gnw = (const float*)d_in[5];
    const float* gnb = (const float*)d_in[6];
    float* out = (float*)d_out;

    cudaFuncSetAttribute(k_gemm_tz, cudaFuncAttributeMaxDynamicSharedMemorySize, TZ_SMEM);
    cudaFuncSetAttribute(k_gemm_pg, cudaFuncAttributeMaxDynamicSharedMemorySize, 4 * PG_STG);

    k_prep<<<1602, 256>>>(Wt, Wp, Wg, Wz);
    k_transX<<<dim3(8, 16, 16), 256>>>(x);
    k_s0<<<128, 256>>>();

    k_gemm_pg<<<dim3(4, 4, 16), 512, 4 * PG_STG>>>();
    k_gemm_tz<<<dim3(8, 4, 16), 256, TZ_SMEM>>>();

    int nblk5 = (B_ * C_ * HW_ / 4 + 255) / 256;
    k_finish<<<nblk5, 256>>>(x, gnw, gnb, out);
}

// round 16
// speedup vs baseline: 1.0301x; 1.0301x over previous
#include <cuda_runtime.h>
#include <cuda_bf16.h>
#include <cuda_fp16.h>
#include <cuda_fp8.h>
#include <cstdint>
#include <math.h>

typedef unsigned long long ull;

#define B_  16
#define C_  1024
#define P_  512
#define HW_ 1024
#define G_  8

#define WSCALE     64.0f
#define INV_WSCALE 0.015625f

// ---------------- scratch (static device globals; no allocation) ----------------
__device__ __half d_z16[(size_t)B_ * C_ * HW_];        // 32 MB fp16
__device__ float d_S[B_ * G_ * 4];                     // moment sums; S0 exact
__device__ float d_gn[B_ * G_ * 2];                    // GN sum / sumsq
__device__ float d_xsum[B_ * C_];                      // per (b,c) spatial sums
__device__ float d_wgsum[G_ * C_];                     // per (g,c) Wg row sums
__device__ float d_wzrs[G_ * 128];                     // rowsum of Wz per (g,oc)

// quantized operands
__device__ uint8_t d_W8[3u * 512u * 1024u];            // fp8 W (x64)
__device__ uint8_t d_XT8[(size_t)B_ * 1024u * 1024u];  // fp8 X^T [b][n][k]
__device__ __nv_bfloat16 d_Wz16[G_ * 128 * 64];        // bf16 Wz

// ---------------- PTX helpers ----------------
__device__ __forceinline__ uint32_t smem_u32(const void* p) {
    uint32_t a;
    asm("{ .reg .u64 t; cvta.to.shared.u64 t, %1; cvt.u32.u64 %0, t; }" : "=r"(a) : "l"(p));
    return a;
}
#define CP_ASYNC16(sa, ga) \
    asm volatile("cp.async.cg.shared.global [%0], [%1], 16;" :: "r"(sa), "l"(ga))
#define CP_COMMIT()   asm volatile("cp.async.commit_group;" ::: "memory")
#define CP_WAIT(n)    asm volatile("cp.async.wait_group %0;" :: "n"(n) : "memory")

__device__ __forceinline__ void ldsm_x4(uint32_t& r0, uint32_t& r1, uint32_t& r2, uint32_t& r3,
                                        uint32_t addr) {
    asm volatile("ldmatrix.sync.aligned.m8n8.x4.shared.b16 {%0,%1,%2,%3}, [%4];"
                 : "=r"(r0), "=r"(r1), "=r"(r2), "=r"(r3) : "r"(addr));
}
// fp8 e4m3 MMA, k=32, f16 accumulators (2 regs)
__device__ __forceinline__ void mma16832h(uint32_t* c, const uint32_t* a, uint32_t b0, uint32_t b1) {
    asm volatile("mma.sync.aligned.m16n8k32.row.col.f16.e4m3.e4m3.f16 "
                 "{%0,%1}, {%2,%3,%4,%5}, {%6,%7}, {%0,%1};"
                 : "+r"(c[0]), "+r"(c[1])
                 : "r"(a[0]), "r"(a[1]), "r"(a[2]), "r"(a[3]), "r"(b0), "r"(b1));
}
__device__ __forceinline__ void mma16816(float* c, const uint32_t* a, uint32_t b0, uint32_t b1) {
    asm volatile("mma.sync.aligned.m16n8k16.row.col.f32.bf16.bf16.f32 "
                 "{%0,%1,%2,%3}, {%4,%5,%6,%7}, {%8,%9}, {%0,%1,%2,%3};"
                 : "+f"(c[0]), "+f"(c[1]), "+f"(c[2]), "+f"(c[3])
                 : "r"(a[0]), "r"(a[1]), "r"(a[2]), "r"(a[3]), "r"(b0), "r"(b1));
}
__device__ __forceinline__ uint8_t to_e4m3(float v) {
    return (uint8_t)__nv_cvt_float_to_fp8(v, __NV_SATFINITE, __NV_E4M3);
}

// =====================================================================
// k_prep: fused prepass — roles by blockIdx.x
// =====================================================================
__global__ void __launch_bounds__(256) k_prep(
    const float* __restrict__ Wt, const float* __restrict__ Wp,
    const float* __restrict__ Wg, const float* __restrict__ Wz)
{
    int bx = blockIdx.x, tid = threadIdx.x;
    if (bx < 1536) {
        int w = bx >> 9, inner = bx & 511;
        const float* W = (w == 0) ? Wt : (w == 1) ? Wp : Wg;
        size_t idx = ((size_t)inner * 256 + tid) * 4;
        float4 v = *(const float4*)&W[idx];
        uint32_t pk = (uint32_t)to_e4m3(v.x * WSCALE)
                    | ((uint32_t)to_e4m3(v.y * WSCALE) << 8)
                    | ((uint32_t)to_e4m3(v.z * WSCALE) << 16)
                    | ((uint32_t)to_e4m3(v.w * WSCALE) << 24);
        *(uint32_t*)(d_W8 + (size_t)w * 524288u + idx) = pk;
    } else if (bx == 1536) {
        for (int i = tid; i < B_ * C_; i += 256) d_xsum[i] = 0.f;
        for (int i = tid; i < 512; i += 256)     d_S[i]    = 0.f;
        if (tid < 256)                            d_gn[tid] = 0.f;
    } else if (bx < 1569) {
        int idx = bx - 1537;
        int g = idx >> 2, c = (idx & 3) * 256 + tid;
        const float* base = Wg + (size_t)g * 64 * 1024 + c;
        float s = 0.f;
#pragma unroll 8
        for (int r = 0; r < 64; r++) s += base[(size_t)r * 1024];
        d_wgsum[g * 1024 + c] = s;
    } else if (bx < 1601) {
        int idx = bx - 1569;
        int base = idx * 2048 + tid * 8;
        float4 v0 = *(const float4*)&Wz[base];
        float4 v1 = *(const float4*)&Wz[base + 4];
        __nv_bfloat162 h0 = __floats2bfloat162_rn(v0.x, v0.y);
        __nv_bfloat162 h1 = __floats2bfloat162_rn(v0.z, v0.w);
        __nv_bfloat162 h2 = __floats2bfloat162_rn(v1.x, v1.y);
        __nv_bfloat162 h3 = __floats2bfloat162_rn(v1.z, v1.w);
        *(uint4*)(d_Wz16 + base) = make_uint4(*(uint32_t*)&h0, *(uint32_t*)&h1,
                                              *(uint32_t*)&h2, *(uint32_t*)&h3);
    } else {
        for (int oc = tid; oc < 1024; oc += 256) {
            const float* p = Wz + (size_t)oc * 64;
            float s = 0.f;
#pragma unroll
            for (int k = 0; k < 64; k++) s += p[k];
            d_wzrs[oc] = s;
        }
    }
}

// =====================================================================
// X transpose -> fp8 [b][n][k], + exact fp32 channel sums (r13 version)
// =====================================================================
__global__ void __launch_bounds__(256) k_transX(const float* __restrict__ x)
{
    __shared__ float Xs[32][132];
    int k0 = blockIdx.x * 32;
    int n0 = blockIdx.y * 128;
    int b  = blockIdx.z;
    int tid = threadIdx.x;
    const float* xb = x + ((size_t)b * 1024 + k0) * 1024 + n0;
#pragma unroll
    for (int i = 0; i < 4; i++) {
        int slot = tid + i * 256;
        int r  = slot >> 5;
        int c4 = (slot & 31) * 4;
        *(float4*)&Xs[r][c4] = *(const float4*)&xb[(size_t)r * 1024 + c4];
    }
    __syncthreads();

    {
        int r = tid >> 3, q = tid & 7;
        float s = 0.f;
#pragma unroll
        for (int c = 0; c < 16; c++) s += Xs[r][q * 16 + c];
        s += __shfl_down_sync(0xffffffffu, s, 4);
        s += __shfl_down_sync(0xffffffffu, s, 2);
        s += __shfl_down_sync(0xffffffffu, s, 1);
        if (q == 0) atomicAdd(&d_xsum[b * 1024 + k0 + r], s);
    }

    int n  = tid >> 1;
    int kh = (tid & 1) * 16;
    uint32_t pk[4];
#pragma unroll
    for (int j = 0; j < 4; j++) {
        pk[j] = (uint32_t)to_e4m3(Xs[kh + 4 * j + 0][n])
              | ((uint32_t)to_e4m3(Xs[kh + 4 * j + 1][n]) << 8)
              | ((uint32_t)to_e4m3(Xs[kh + 4 * j + 2][n]) << 16)
              | ((uint32_t)to_e4m3(Xs[kh + 4 * j + 3][n]) << 24);
    }
    size_t off = ((size_t)b * 1024 + n0 + n) * 1024 + k0 + kh;
    *(uint4*)(d_XT8 + off) = make_uint4(pk[0], pk[1], pk[2], pk[3]);
}

// =====================================================================
// Exact S0[b][g] = sum_c wgsum[g][c] * xsum[b][c]
// =====================================================================
__global__ void __launch_bounds__(256) k_s0()
{
    int bg = blockIdx.x;
    int b = bg >> 3, g = bg & 7;
    int tid = threadIdx.x;
    float s = 0.f;
    for (int c = tid; c < 1024; c += 256)
        s += d_wgsum[g * 1024 + c] * d_xsum[b * 1024 + c];
#pragma unroll
    for (int off = 16; off > 0; off >>= 1)
        s += __shfl_down_sync(0xffffffffu, s, off);
    __shared__ float red[8];
    if ((tid & 31) == 0) red[tid >> 5] = s;
    __syncthreads();
    if (tid == 0) {
        float S = 0.f;
#pragma unroll
        for (int i = 0; i < 8; i++) S += red[i];
        d_S[bg * 4 + 0] = S;
    }
}

// =====================================================================
// GEMM-PG (fp8, f16 acc): CTA 128m x 256n, 512 thr / 16 warps
// (warp tile 32m x 64n), 4-stage cp.async pipeline.  (r15-measured win)
// =====================================================================
#define NCH        16
#define ROWB       80
#define TILE_B     10240           // 128 rows * 80B
#define PG_STG     40960           // Ap + Ag + B(256)

__device__ __forceinline__ void pg_load_chunk(
    uint32_t sb, const uint8_t* gAp, const uint8_t* gAg,
    const uint8_t* gB, int k0, int tid)
{
#pragma unroll
    for (int i = 0; i < 4; i++) {
        int unit = tid + i * 512;            // 0..2047
        const uint8_t* src;
        uint32_t dst;
        if (unit < 512) {
            int r = unit >> 2, u = unit & 3;
            dst = sb + (uint32_t)r * ROWB + (uint32_t)u * 16;
            src = gAp + (size_t)r * 1024 + k0 + u * 16;
        } else if (unit < 1024) {
            int rem = unit - 512;
            int r = rem >> 2, u = rem & 3;
            dst = sb + TILE_B + (uint32_t)r * ROWB + (uint32_t)u * 16;
            src = gAg + (size_t)r * 1024 + k0 + u * 16;
        } else {
            int rem = unit - 1024;           // 0..1023 -> 256 rows
            int r = rem >> 2, u = rem & 3;
            dst = sb + 2 * TILE_B + (uint32_t)r * ROWB + (uint32_t)u * 16;
            src = gB + (size_t)r * 1024 + k0 + u * 16;
        }
        CP_ASYNC16(dst, (const void*)src);
    }
}

__global__ void __launch_bounds__(512, 1) k_gemm_pg()
{
    extern __shared__ char smraw[];
    uint32_t sbase = smem_u32(smraw);

    const int tid  = threadIdx.x;
    const int wid  = tid >> 5;
    const int lane = tid & 31;
    const int wm   = wid & 3;       // 4 m-subtiles of 32
    const int wn   = wid >> 2;      // 4 n-subtiles of 64

    const int n0 = blockIdx.x * 256;
    const int m0 = blockIdx.y * 128;
    const int b  = blockIdx.z;

    const uint8_t* gAp = d_W8 + 1u * 524288u + (size_t)m0 * 1024;
    const uint8_t* gAg = d_W8 + 2u * 524288u + (size_t)m0 * 1024;
    const uint8_t* gB  = d_XT8 + ((size_t)b * 1024 + n0) * 1024;

    uint32_t accp[2][8][2], accg[2][8][2];      // f16x2 accumulators (warp 32x64)
#pragma unroll
    for (int i = 0; i < 2; i++)
#pragma unroll
        for (int j = 0; j < 8; j++) {
            accp[i][j][0] = 0u; accp[i][j][1] = 0u;
            accg[i][j][0] = 0u; accg[i][j][1] = 0u;
        }

    const uint32_t aLane = (uint32_t)((wm * 32 + (lane & 15)) * ROWB + (lane >> 4) * 16);
    const int bgrp = lane >> 3;
    const uint32_t bLane = (uint32_t)((wn * 64 + (bgrp >> 1) * 8 + (lane & 7)) * ROWB + (bgrp & 1) * 16);

    pg_load_chunk(sbase, gAp, gAg, gB, 0, tid);
    CP_COMMIT();
    pg_load_chunk(sbase + PG_STG, gAp, gAg, gB, 64, tid);
    CP_COMMIT();
    pg_load_chunk(sbase + 2 * PG_STG, gAp, gAg, gB, 128, tid);
    CP_COMMIT();

    int stg = 0;
    for (int j = 0; j < NCH; j++) {
        if (j <= NCH - 3)      CP_WAIT(2);
        else if (j == NCH - 2) CP_WAIT(1);
        else                   CP_WAIT(0);
        __syncthreads();
        if (j + 3 < NCH) {
            int ns = stg + 3; if (ns >= 4) ns -= 4;
            pg_load_chunk(sbase + (uint32_t)ns * PG_STG, gAp, gAg, gB, (j + 3) * 64, tid);
            CP_COMMIT();
        }
        const uint32_t sb = sbase + (uint32_t)stg * PG_STG;
#pragma unroll
        for (int s = 0; s < 2; s++) {
            const uint32_t kb = (uint32_t)s * 32;
            uint32_t Ap[2][4], Ag[2][4], Bv[8][2];
#pragma unroll
            for (int i = 0; i < 2; i++) {
                ldsm_x4(Ap[i][0], Ap[i][1], Ap[i][2], Ap[i][3],
                        sb + 0 * TILE_B + aLane + (uint32_t)i * (16 * ROWB) + kb);
                ldsm_x4(Ag[i][0], Ag[i][1], Ag[i][2], Ag[i][3],
                        sb + 1 * TILE_B + aLane + (uint32_t)i * (16 * ROWB) + kb);
            }
#pragma unroll
            for (int jp = 0; jp < 4; jp++)
                ldsm_x4(Bv[jp * 2][0], Bv[jp * 2][1], Bv[jp * 2 + 1][0], Bv[jp * 2 + 1][1],
                        sb + 2 * TILE_B + bLane + (uint32_t)jp * (16 * ROWB) + kb);
#pragma unroll
            for (int i = 0; i < 2; i++)
#pragma unroll
                for (int jj = 0; jj < 8; jj++) {
                    mma16832h(accp[i][jj], Ap[i], Bv[jj][0], Bv[jj][1]);
                    mma16832h(accg[i][jj], Ag[i], Bv[jj][0], Bv[jj][1]);
                }
        }
        if (++stg == 4) stg = 0;
    }

    // moment epilogue (S1..S3; unscale W factor on p and g)
    {
        float s1 = 0.f, s2 = 0.f, s3 = 0.f;
#pragma unroll
        for (int i = 0; i < 2; i++)
#pragma unroll
            for (int jj = 0; jj < 8; jj++)
#pragma unroll
                for (int h = 0; h < 2; h++) {
                    float2 pv2 = __half22float2(*(__half2*)&accp[i][jj][h]);
                    float2 gv2 = __half22float2(*(__half2*)&accg[i][jj][h]);
#pragma unroll
                    for (int l = 0; l < 2; l++) {
                        float pv = (l ? pv2.y : pv2.x) * INV_WSCALE;
                        float gv = (l ? gv2.y : gv2.x) * INV_WSCALE;
                        float t1 = pv * gv; s1 += t1;
                        t1 *= pv; s2 += t1;
                        t1 *= pv; s3 += t1;
                    }
                }
#pragma unroll
        for (int off = 16; off > 0; off >>= 1) {
            s1 += __shfl_down_sync(0xffffffffu, s1, off);
            s2 += __shfl_down_sync(0xffffffffu, s2, off);
            s3 += __shfl_down_sync(0xffffffffu, s3, off);
        }
        if (lane == 0) {
            int g = (m0 >> 6) + (wm >> 1);
            float* Sp = d_S + (b * 8 + g) * 4;
            atomicAdd(Sp + 1, s1);
            atomicAdd(Sp + 2, s2);
            atomicAdd(Sp + 3, s3);
        }
    }
}

// =====================================================================
// GEMM-TZ (fp8 f16-acc + fused z) — r13 version: K=64 chunks, 3-stage,
// 73.7 KB smem (2 CTAs/SM).  t = Wt @ X, y'' transform, z-GEMM, GN sums.
// =====================================================================
#define T_STG     20480
#define AZ_OFF    0
#define TS_OFF    36864
#define ZT_STRIDE 18432          // 128 rows * 144 B
#define ROWZ      144
#define TZ_SMEM   73728

__device__ __forceinline__ void t_load_chunk(
    uint32_t sb, const uint8_t* gA, const uint8_t* gB, int k0, int tid)
{
#pragma unroll
    for (int i = 0; i < 4; i++) {
        int unit = tid + i * 256;
        int tile = unit >> 9;
        int rem  = unit & 511;
        int r = rem >> 2, u = rem & 3;
        uint32_t dst = sb + (uint32_t)tile * TILE_B + (uint32_t)r * ROWB + (uint32_t)u * 16;
        const uint8_t* src = (tile == 0 ? gA : gB) + (size_t)r * 1024 + k0 + u * 16;
        CP_ASYNC16(dst, (const void*)src);
    }
}

__global__ void __launch_bounds__(256, 2) k_gemm_tz()
{
    extern __shared__ char smraw[];
    uint32_t sbase = smem_u32(smraw);

    const int tid  = threadIdx.x;
    const int wid  = tid >> 5;
    const int lane = tid & 31;
    const int wm   = wid & 1;
    const int wn   = wid >> 1;

    const int n0 = blockIdx.x * 128;
    const int m0 = blockIdx.y * 128;
    const int b  = blockIdx.z;

    const uint8_t* gA = d_W8 + (size_t)m0 * 1024;
    const uint8_t* gB = d_XT8 + ((size_t)b * 1024 + n0) * 1024;

    uint32_t acc[4][4][2];                       // f16x2 accumulators
#pragma unroll
    for (int i = 0; i < 4; i++)
#pragma unroll
        for (int j = 0; j < 4; j++) { acc[i][j][0] = 0u; acc[i][j][1] = 0u; }

    const uint32_t aLane = (uint32_t)((wm * 64 + (lane & 15)) * ROWB + (lane >> 4) * 16);
    const int bg = lane >> 3;
    const uint32_t bLane = (uint32_t)((wn * 32 + (bg >> 1) * 8 + (lane & 7)) * ROWB + (bg & 1) * 16);

    t_load_chunk(sbase, gA, gB, 0, tid);
    CP_COMMIT();
    t_load_chunk(sbase + T_STG, gA, gB, 64, tid);
    CP_COMMIT();

    int stg = 0;
    for (int j = 0; j < NCH; j++) {
        if (j + 1 < NCH) CP_WAIT(1); else CP_WAIT(0);
        __syncthreads();
        if (j + 2 < NCH) {
            int ns = stg + 2; if (ns >= 3) ns -= 3;
            t_load_chunk(sbase + (uint32_t)ns * T_STG, gA, gB, (j + 2) * 64, tid);
            CP_COMMIT();
        }
        const uint32_t sb = sbase + (uint32_t)stg * T_STG;

        uint32_t A[2][4][4], Bv[2][4][2];
#pragma unroll
        for (int s = 0; s < 2; s++) {
            const uint32_t kb = (uint32_t)s * 32;
#pragma unroll
            for (int i = 0; i < 4; i++)
                ldsm_x4(A[s][i][0], A[s][i][1], A[s][i][2], A[s][i][3],
                        sb + aLane + (uint32_t)i * (16 * ROWB) + kb);
#pragma unroll
            for (int jp = 0; jp < 2; jp++)
                ldsm_x4(Bv[s][jp * 2][0], Bv[s][jp * 2][1],
                        Bv[s][jp * 2 + 1][0], Bv[s][jp * 2 + 1][1],
                        sb + TILE_B + bLane + (uint32_t)jp * (16 * ROWB) + kb);
        }
#pragma unroll
        for (int s = 0; s < 2; s++)
#pragma unroll
            for (int i = 0; i < 4; i++)
#pragma unroll
                for (int jj = 0; jj < 4; jj++)
                    mma16832h(acc[i][jj], A[s][i], Bv[s][jj][0], Bv[s][jj][1]);
        if (++stg == 3) stg = 0;
    }
    __syncthreads();        // all warps done reading stage smem

    const float tg   = 2.0f * 1e-4f;
    const float beta = expf(-tg);

    // ---- epilogue A: y'' transform + transposed smem stage [n][ch] ----
    {
        const int gidx = (b * 8) + (m0 >> 6) + wm;     // warp's group
        const float c1 = beta * tg * d_S[gidx * 4 + 1];
        const float c2 = beta * (tg * tg * 0.5f) * d_S[gidx * 4 + 2];
        const float c3 = beta * (tg * tg * tg * (1.f / 6.f)) * d_S[gidx * 4 + 3];
        const float a2 = c2 / c1, a3 = c3 / c1;

        char* Tsb = smraw + TS_OFF + wm * ZT_STRIDE;
        const int mq = lane >> 2;
        const int nq = (lane & 3) * 2;
#pragma unroll
        for (int i = 0; i < 4; i++)
#pragma unroll
            for (int jj = 0; jj < 4; jj++)
#pragma unroll
                for (int h = 0; h < 2; h++) {
                    float2 tv2 = __half22float2(*(__half2*)&acc[i][jj][h]);
#pragma unroll
                    for (int l = 0; l < 2; l++) {
                        int chl = (i * 16 + mq + (h << 3)) & 63;
                        int n   = wn * 32 + jj * 8 + nq + l;
                        float t = (l ? tv2.y : tv2.x) * INV_WSCALE;
                        float y = t * (1.f + a2 * t + a3 * t * t);
                        *(__nv_bfloat16*)(Tsb + n * ROWZ + chl * 2) = __float2bfloat16(y);
                    }
                }
    }
    // ---- epilogue B: async-load Wz tiles for the 2 groups ----
    {
        const int gb = (m0 >> 6);
#pragma unroll
        for (int i = 0; i < 8; i++) {
            int unit = tid + i * 256;             // 0..2047
            int tile = unit >> 10;
            int rem  = unit & 1023;
            int r = rem >> 3, u = rem & 7;
            CP_ASYNC16(sbase + AZ_OFF + (uint32_t)tile * ZT_STRIDE + (uint32_t)r * ROWZ + (uint32_t)u * 16,
                       (const void*)(d_Wz16 + (gb + tile) * 8192 + r * 64 + u * 8));
        }
        CP_COMMIT();
        CP_WAIT(0);
        __syncthreads();
    }
    // ---- epilogue C: z-GEMM, 2 jobs per warp (job = 64oc x 32n of one group) ----
#pragma unroll
    for (int jb = 0; jb < 2; jb++) {
        const int job  = wid * 2 + jb;            // 0..15
        const int gloc = job >> 3;
        const int och  = (job & 7) >> 2;
        const int nq   = job & 3;
        const int g    = (m0 >> 6) + gloc;
        const int gidx = b * 8 + g;
        const float c0 = beta * d_S[gidx * 4 + 0];
        const float c1 = beta * tg * d_S[gidx * 4 + 1];

        const uint32_t aBase = sbase + AZ_OFF + (uint32_t)gloc * ZT_STRIDE;
        const uint32_t bBase = sbase + TS_OFF + (uint32_t)gloc * ZT_STRIDE;
        const uint32_t aL = (uint32_t)((och * 64 + (lane & 15)) * ROWZ + (lane >> 4) * 16);
        const int bq = lane >> 3;
        const uint32_t bL = (uint32_t)((nq * 32 + (bq >> 1) * 8 + (lane & 7)) * ROWZ + (bq & 1) * 16);

        float az[4][4][4];
#pragma unroll
        for (int i = 0; i < 4; i++)
#pragma unroll
            for (int jj = 0; jj < 4; jj++)
#pragma unroll
                for (int q = 0; q < 4; q++) az[i][jj][q] = 0.f;

#pragma unroll
        for (int ks = 0; ks < 4; ks++) {
            const uint32_t kb = (uint32_t)ks * 32;
            uint32_t A[4][4], Bv[4][2];
#pragma unroll
            for (int i = 0; i < 4; i++)
                ldsm_x4(A[i][0], A[i][1], A[i][2], A[i][3],
                        aBase + aL + (uint32_t)i * (16 * ROWZ) + kb);
#pragma unroll
            for (int jp = 0; jp < 2; jp++)
                ldsm_x4(Bv[jp * 2][0], Bv[jp * 2][1], Bv[jp * 2 + 1][0], Bv[jp * 2 + 1][1],
                        bBase + bL + (uint32_t)jp * (16 * ROWZ) + kb);
#pragma unroll
            for (int i = 0; i < 4; i++)
#pragma unroll
                for (int jj = 0; jj < 4; jj++)
                    mma16816(az[i][jj], A[i], Bv[jj][0], Bv[jj][1]);
        }

        // write z (fp16) + GN partials for this job
        const int mloc = och * 64 + (lane >> 2);
        const int nloc = nq * 32 + (lane & 3) * 2;
        float rsv[4][2];
#pragma unroll
        for (int i = 0; i < 4; i++)
#pragma unroll
            for (int h = 0; h < 2; h++)
                rsv[i][h] = d_wzrs[g * 128 + mloc + i * 16 + h * 8];

        __half* zb = d_z16 + ((size_t)(b * 1024 + g * 128)) * 1024;
        float ls = 0.f, lss = 0.f;
#pragma unroll
        for (int i = 0; i < 4; i++)
#pragma unroll
            for (int jj = 0; jj < 4; jj++)
#pragma unroll
                for (int h = 0; h < 2; h++) {
                    float z0 = c0 * rsv[i][h] + c1 * az[i][jj][2 * h + 0];
                    float z1 = c0 * rsv[i][h] + c1 * az[i][jj][2 * h + 1];
                    ls += z0 + z1;
                    lss += z0 * z0 + z1 * z1;
                    int oc = mloc + i * 16 + h * 8;
                    int n  = nloc + jj * 8;
                    *(__half2*)(zb + (size_t)oc * 1024 + n0 + n) = __floats2half2_rn(z0, z1);
                }
#pragma unroll
        for (int off = 16; off > 0; off >>= 1) {
            ls  += __shfl_down_sync(0xffffffffu, ls, off);
            lss += __shfl_down_sync(0xffffffffu, lss, off);
        }
        if (lane == 0) {
            atomicAdd(&d_gn[gidx * 2 + 0], ls);
            atomicAdd(&d_gn[gidx * 2 + 1], lss);
        }
    }
}

// =====================================================================
// finish: out = (z - mean)*rstd*gn_w + gn_b + x   (z in fp16)
// =====================================================================
__global__ void __launch_bounds__(256) k_finish(
    const float* __restrict__ x, const float* __restrict__ gn_w,
    const float* __restrict__ gn_b, float* __restrict__ out)
{
    int i4 = blockIdx.x * 256 + threadIdx.x;
    if (i4 >= (B_ * C_ * HW_) / 4) return;
    size_t idx = (size_t)i4 * 4;
    int ch = (int)((idx >> 10) & 1023);
    int b  = (int)(idx >> 20);
    int bg = b * 8 + (ch >> 7);
    const float invN = 1.0f / 131072.0f;
    float s  = d_gn[bg * 2 + 0];
    float ss = d_gn[bg * 2 + 1];
    float mean = s * invN;
    float var  = ss * invN - mean * mean;
    float rstd = rsqrtf(var + 1e-5f);
    float a = gn_w[ch] * rstd;
    float c = gn_b[ch] - mean * a;
    uint2 zr = *(const uint2*)&d_z16[idx];
    float2 z01 = __half22float2(*(__half2*)&zr.x);
    float2 z23 = __half22float2(*(__half2*)&zr.y);
    float4 xv = *(const float4*)&x[idx];
    float4 o;
    o.x = z01.x * a + c + xv.x;
    o.y = z01.y * a + c + xv.y;
    o.z = z23.x * a + c + xv.z;
    o.w = z23.y * a + c + xv.w;
    *(float4*)&out[idx] = o;
}

// =====================================================================
extern "C" void kernel_launch(void* const* d_in, const int* in_sizes, int n_in,
                              void* d_out, int out_size)
{
    const float* x   = (const float*)d_in[0];
    const float* Wt  = (const float*)d_in[1];
    const float* Wp  = (const float*)d_in[2];
    const float* Wg  = (const float*)d_in[3];
    const float* Wz  = (const float*)d_in[4];
    const float* gnw = (const float*)d_in[5];
    const float* gnb = (const float*)d_in[6];
    float* out = (float*)d_out;

    cudaFuncSetAttribute(k_gemm_tz, cudaFuncAttributeMaxDynamicSharedMemorySize, TZ_SMEM);
    cudaFuncSetAttribute(k_gemm_pg, cudaFuncAttributeMaxDynamicSharedMemorySize, 4 * PG_STG);

    k_prep<<<1602, 256>>>(Wt, Wp, Wg, Wz);
    k_transX<<<dim3(32, 8, 16), 256>>>(x);
    k_s0<<<128, 256>>>();

    k_gemm_pg<<<dim3(4, 4, 16), 512, 4 * PG_STG>>>();
    k_gemm_tz<<<dim3(8, 4, 16), 256, TZ_SMEM>>>();

    int nblk5 = (B_ * C_ * HW_ / 4 + 255) / 256;
    k_finish<<<nblk5, 256>>>(x, gnw, gnb, out);
}